// round 16
// baseline (speedup 1.0000x reference)
#include <cuda_runtime.h>
#include <stdint.h>
#include <math.h>

#define KOUT 49
#define MAXT 32
#define SAMPLES_PER_BLK 64               // 2 samples per thread: pair (lane, lane+32)
#define THREADS_PER_BLK 224              // 7 warps: warp w -> mu = w
// X region: 32 sample-PAIRS, interleaved. Element c of pair p: words p*198 + 2c (s0), +1 (s1).
// 198 = 2*99; per-16-lane phase LDS.64 banks: 6*lane mod 32 -> 16 distinct even
// residues -> disjoint (even,odd) bank pairs -> conflict-free.
#define XSTR2 198
#define X2B8 392                         // byte offset of X2 row 0 within pair blob (49 elements * 8B)
#define OBASE (32 * XSTR2)               // 6336 words
#define OUTSTR 65                        // odd -> conflict-free transposed staging
#define SMEM_WORDS (OBASE + KOUT * OUTSTR)   // 9521 words = 38084 B

// ---- packed f32x2 helpers (sm_103a FFMA2 via PTX) ----
__device__ __forceinline__ unsigned long long pk2(float lo, float hi) {
    unsigned long long r;
    asm("mov.b64 %0, {%1, %2};" : "=l"(r)
        : "r"(__float_as_uint(lo)), "r"(__float_as_uint(hi)));
    return r;
}
__device__ __forceinline__ unsigned long long fma2(unsigned long long a,
                                                   unsigned long long b,
                                                   unsigned long long c) {
    unsigned long long r;
    asm("fma.rn.f32x2 %0, %1, %2, %3;" : "=l"(r) : "l"(a), "l"(b), "l"(c));
    return r;
}
__device__ __forceinline__ unsigned long long mul2(unsigned long long a,
                                                   unsigned long long b) {
    unsigned long long r;
    asm("mul.rn.f32x2 %0, %1, %2;" : "=l"(r) : "l"(a), "l"(b));
    return r;
}
__device__ __forceinline__ void upk2(unsigned long long v, float& lo, float& hi) {
    unsigned l, h;
    asm("mov.b64 {%0, %1}, %2;" : "=r"(l), "=r"(h) : "l"(v));
    lo = __uint_as_float(l); hi = __uint_as_float(h);
}

// ---------------------------------------------------------------------------
// Single FUSED kernel. O(1) table recovery (R13):
//   n = Ttot^2 => Ttot = round(sqrt(n)); focc[v] v=0..6 in first Ttot<=224
//   entries => one predicated atomicMin round. seg(mu) = Ttot*focc[mu].
// Coefficients from products only (A = mult[0] = c0^2).
// Stage-1: <=2 terms per (mu, m2-row) (validated R8-R14), uint4 slot holding
// BYTE offsets into the 8B-per-element pair blob (m1*56 — used directly, the
// R15 bug was an extra *2 at the use site). Stage-2: dense D pre-duplicated
// as (d,d) f32x2 pairs.
// ---------------------------------------------------------------------------
__global__ void __launch_bounds__(THREADS_PER_BLK, 3)
wigner_fused(const float* __restrict__ X1, const float* __restrict__ X2,
             const float* __restrict__ mult,
             const int* __restrict__ m1,  const int* __restrict__ m1p,
             const int* __restrict__ m2,  const int* __restrict__ m2p,
             const int* __restrict__ mub,
             float* __restrict__ out, int N, int n)
{
    __shared__ __align__(16) float sm[SMEM_WORDS];
    __shared__ __align__(16) uint4 s_gslot[49];
    __shared__ __align__(16) unsigned long long s_D2[KOUT * 8];  // (d,d) pairs, row padded to 8
    __shared__ int s_focc[8];
    __shared__ int s_cnt[KOUT];
    __shared__ int s_sT[8];

    int tid  = threadIdx.x;
    int lane = tid & 31;
    int mu   = tid >> 5;
    int base = blockIdx.x * SAMPLES_PER_BLK;
    int nvalid = N - base; if (nvalid > SAMPLES_PER_BLK) nvalid = SAMPLES_PER_BLK;
    int total = nvalid * KOUT;
    bool full = (nvalid == SAMPLES_PER_BLK);

    const float* g1 = X1 + (size_t)base * KOUT;
    const float* g2 = X2 + (size_t)base * KOUT;

    // ---- init shared table state ----
    if (tid < 8)    s_focc[tid] = 0x7fffffff;
    if (tid < KOUT) { s_cnt[tid] = 0; s_gslot[tid] = make_uint4(0u,0u,0u,0u); }
    for (int i = tid; i < KOUT * 8; i += THREADS_PER_BLK) s_D2[i] = 0ULL;

    // ---- issue X staging LDGs early (MLP=28); latency hides the table build
    float r1v[14], r2v[14];
    if (full) {
        #pragma unroll
        for (int k = 0; k < 14; k++) {
            int i = tid + k * THREADS_PER_BLK;
            r1v[k] = g1[i];
            r2v[k] = g2[i];
        }
    }
    __syncthreads();

    // ---- focc recovery: ONE round over the first <=224 aligned entries
    if (tid < n) {
        int v = mub[tid];
        if (v < 7) atomicMin(&s_focc[v], tid);
    }

    // ---- STS the X data INTERLEAVED (loads arrive under the atomic round)
    if (full) {
        #pragma unroll
        for (int k = 0; k < 14; k++) {
            int i = tid + k * THREADS_PER_BLK;
            int s = i / KOUT;
            int c = i - s * KOUT;
            int p = s & 31, h = s >> 5;
            sm[p * XSTR2 + 2 * c + h]            = r1v[k];
            sm[p * XSTR2 + 2 * (c + KOUT) + h]   = r2v[k];
        }
    }
    __syncthreads();

    if (tid == 0) {
        int Ttot = (int)(sqrtf((float)n) + 0.5f);   // n = Ttot^2 exactly
        s_focc[0] = 0;
        s_sT[7] = Ttot;
        for (int v = 0; v < 6; v++) s_sT[v] = s_focc[v + 1] - s_focc[v];
        s_sT[6] = Ttot - s_focc[6];
        for (int v = 0; v < 7; v++) if (s_sT[v] > MAXT) s_sT[v] = MAXT;
    }
    __syncthreads();

    // ---- build tables (one thread per (mu, t) slot; index arrays L2-hot)
    {
        float A = mult[0];
        int Ttot = s_sT[7];
        int t = lane;
        if (t < s_sT[mu]) {
            int j = Ttot * (s_focc[mu] + t);               // (mu, t, 0, 0)
            int r2 = m2[j];
            int pos = atomicAdd(&s_cnt[mu * 7 + r2], 1);
            if (pos < 2) {
                unsigned* slot = (unsigned*)&s_gslot[mu * 7 + r2];
                slot[pos * 2]     = (unsigned)(m1[j] * 56);    // byte off: row r1 * 7 elem * 8B
                slot[pos * 2 + 1] = __float_as_uint(mult[j]);
            }
            int j2 = s_focc[mu] + t;                        // (0, 0, mup=mu, t')
            float d = mult[j2] / A;                         // unique -> plain store
            s_D2[(m1p[j2] * 7 + m2p[j2]) * 8 + mu] = pk2(d, d);
        }
    }
    __syncthreads();
    // canonical slot order (deterministic regardless of atomic race)
    if (tid < 49) {
        uint4 e = s_gslot[tid];
        if (e.w != 0u && e.x > e.z) s_gslot[tid] = make_uint4(e.z, e.w, e.x, e.y);
    }

    // ---- slow-path staging for the tail block
    if (!full) {
        for (int i = tid; i < OBASE; i += THREADS_PER_BLK) sm[i] = 0.0f;
        __syncthreads();
        for (int i = tid; i < total; i += THREADS_PER_BLK) {
            int s = i / KOUT;
            int c = i - s * KOUT;
            int p = s & 31, h = s >> 5;
            sm[p * XSTR2 + 2 * c + h]          = g1[i];
            sm[p * XSTR2 + 2 * (c + KOUT) + h] = g2[i];
        }
    }
    __syncthreads();

    // ================== compute core: packed LDS.64 + FFMA2 ==================
    {
        const char* xc = (const char*)(sm + lane * XSTR2);   // pair blob, 8B/element
        const uint4* gs = s_gslot + mu * 7;
        unsigned long long accp[7];
        #pragma unroll
        for (int q = 0; q < 7; q++) accp[q] = 0ULL;

        // ================= PASS A : rows a = 0..3 =================
        {
            unsigned long long WA[28];
            #pragma unroll
            for (int i = 0; i < 28; i++) WA[i] = 0ULL;
            #pragma unroll 1
            for (int g = 0; g < 7; g++) {
                uint4 e = gs[g];                               // uniform
                float c0 = __uint_as_float(e.y);
                float c1 = __uint_as_float(e.w);
                unsigned long long c0d = pk2(c0, c0);
                unsigned long long c1d = pk2(c1, c1);
                const unsigned long long* ra = (const unsigned long long*)(xc + e.x);  // FIXED: no *2
                const unsigned long long* rb = (const unsigned long long*)(xc + e.z);
                unsigned long long u[4];
                #pragma unroll
                for (int a = 0; a < 4; a++)
                    u[a] = fma2(c1d, rb[a], mul2(c0d, ra[a]));
                const unsigned long long* r2p =
                    (const unsigned long long*)(xc + X2B8 + g * 56);
                #pragma unroll
                for (int b = 0; b < 7; b++) {
                    unsigned long long xp = r2p[b];            // packed (s0,s1): one LDS.64
                    WA[0 * 7 + b] = fma2(u[0], xp, WA[0 * 7 + b]);
                    WA[1 * 7 + b] = fma2(u[1], xp, WA[1 * 7 + b]);
                    WA[2 * 7 + b] = fma2(u[2], xp, WA[2 * 7 + b]);
                    WA[3 * 7 + b] = fma2(u[3], xp, WA[3 * 7 + b]);
                }
            }
            #pragma unroll
            for (int i = 0; i < 28; i++) {
                const ulonglong2* dp = (const ulonglong2*)(s_D2 + i * 8);
                ulonglong2 q0 = dp[0];
                ulonglong2 q1 = dp[1];
                ulonglong2 q2 = dp[2];
                unsigned long long q3 = s_D2[i * 8 + 6];
                unsigned long long w = WA[i];
                accp[0] = fma2(q0.x, w, accp[0]);
                accp[1] = fma2(q0.y, w, accp[1]);
                accp[2] = fma2(q1.x, w, accp[2]);
                accp[3] = fma2(q1.y, w, accp[3]);
                accp[4] = fma2(q2.x, w, accp[4]);
                accp[5] = fma2(q2.y, w, accp[5]);
                accp[6] = fma2(q3,   w, accp[6]);
            }
        }

        // ================= PASS B : rows a = 4..6 =================
        {
            unsigned long long WB[21];
            #pragma unroll
            for (int i = 0; i < 21; i++) WB[i] = 0ULL;
            #pragma unroll 1
            for (int g = 0; g < 7; g++) {
                uint4 e = gs[g];
                float c0 = __uint_as_float(e.y);
                float c1 = __uint_as_float(e.w);
                unsigned long long c0d = pk2(c0, c0);
                unsigned long long c1d = pk2(c1, c1);
                const unsigned long long* ra = (const unsigned long long*)(xc + e.x);  // FIXED
                const unsigned long long* rb = (const unsigned long long*)(xc + e.z);
                unsigned long long u[3];
                #pragma unroll
                for (int a = 0; a < 3; a++)
                    u[a] = fma2(c1d, rb[4 + a], mul2(c0d, ra[4 + a]));
                const unsigned long long* r2p =
                    (const unsigned long long*)(xc + X2B8 + g * 56);
                #pragma unroll
                for (int b = 0; b < 7; b++) {
                    unsigned long long xp = r2p[b];
                    WB[0 * 7 + b] = fma2(u[0], xp, WB[0 * 7 + b]);
                    WB[1 * 7 + b] = fma2(u[1], xp, WB[1 * 7 + b]);
                    WB[2 * 7 + b] = fma2(u[2], xp, WB[2 * 7 + b]);
                }
            }
            #pragma unroll
            for (int i = 0; i < 21; i++) {
                const ulonglong2* dp = (const ulonglong2*)(s_D2 + (28 + i) * 8);
                ulonglong2 q0 = dp[0];
                ulonglong2 q1 = dp[1];
                ulonglong2 q2 = dp[2];
                unsigned long long q3 = s_D2[(28 + i) * 8 + 6];
                unsigned long long w = WB[i];
                accp[0] = fma2(q0.x, w, accp[0]);
                accp[1] = fma2(q0.y, w, accp[1]);
                accp[2] = fma2(q1.x, w, accp[2]);
                accp[3] = fma2(q1.y, w, accp[3]);
                accp[4] = fma2(q2.x, w, accp[4]);
                accp[5] = fma2(q2.y, w, accp[5]);
                accp[6] = fma2(q3,   w, accp[6]);
            }
        }

        // stage outputs transposed (stride 65 odd -> conflict-free)
        #pragma unroll
        for (int mup = 0; mup < 7; mup++) {
            float a0, a1;
            upk2(accp[mup], a0, a1);
            sm[OBASE + (mu * 7 + mup) * OUTSTR + lane]      = a0;
            sm[OBASE + (mu * 7 + mup) * OUTSTR + lane + 32] = a1;
        }
    }
    __syncthreads();

    // coalesced flush
    float* go = out + (size_t)base * KOUT;
    for (int i = tid; i < total; i += THREADS_PER_BLK) {
        int s = i / KOUT;
        int c = i - s * KOUT;
        go[i] = sm[OBASE + c * OUTSTR + s];
    }
}

// ---------------------------------------------------------------------------
extern "C" void kernel_launch(void* const* d_in, const int* in_sizes, int n_in,
                              void* d_out, int out_size)
{
    const float* X1   = (const float*)d_in[0];
    const float* X2   = (const float*)d_in[1];
    const float* mult = (const float*)d_in[2];
    const int*   m1   = (const int*)d_in[3];
    const int*   m1p  = (const int*)d_in[4];
    const int*   m2   = (const int*)d_in[5];
    const int*   m2p  = (const int*)d_in[6];
    const int*   mub  = (const int*)d_in[7];

    int n_aligned = in_sizes[2];
    int N = in_sizes[0] / KOUT;

    int grid = (N + SAMPLES_PER_BLK - 1) / SAMPLES_PER_BLK;
    wigner_fused<<<grid, THREADS_PER_BLK>>>(X1, X2, mult, m1, m1p, m2, m2p, mub,
                                            (float*)d_out, N, n_aligned);
}

// round 17
// speedup vs baseline: 1.0096x; 1.0096x over previous
#include <cuda_runtime.h>
#include <stdint.h>
#include <math.h>

#define KOUT 49
#define MAXT 32
#define SAMPLES_PER_BLK 32               // 1 sample per thread (lane)
#define THREADS_PER_BLK 224              // 7 warps: warp w -> mu = w
#define XSTR 99                          // per-sample X blob: X1[0..48], X2[49..97], pad (odd -> conflict-free)
#define X2B 196                          // byte offset of X2 row 0 in blob
#define OBASE (SAMPLES_PER_BLK * XSTR)   // 3168 words
#define OUTSTR 33                        // odd -> conflict-free transposed staging
#define SMEM_WORDS (OBASE + KOUT * OUTSTR)   // 4785 words = 19140 B

// ---------------------------------------------------------------------------
// Single FUSED kernel; every block rebuilds the tiny tables in shared memory,
// overlapped with the X staging loads. O(1) table recovery (R13):
//   n = Ttot^2 exactly  => Ttot = round(sqrt(n))
//   focc[v] v=0..6 lie in the first Ttot<=224 aligned entries => one
//   predicated atomicMin round over mub[tid] recovers them.
//   seg(mu) = Ttot*focc[mu]; T[v] = focc[v+1]-focc[v], T[6] = Ttot-focc[6]
// Coefficients from products only (A = mult[0] = c0^2):
//   c_hat(mu,t) = mult[Ttot*(focc[mu]+t)], d_hat = mult[focc[mup]+t']/A.
// Stage-1: <=2 terms per (mu, m2-row) (validated R8-R16), uint4 slot
// {x1_off_a, c_a, x1_off_b, c_b}, canonical order.
// Stage-2: dense D[i][mup], (m1p,m2p) unique per mup -> plain stores.
//
// R17 core: 1 sample/thread, SINGLE pass over full W[49] (no two-pass
// redundancy), rolled 7-group loop, 96-reg budget (3 blocks/SM) -> no spills.
// 625 blocks * 7 warps = 4375 warps for latency hiding.
// ---------------------------------------------------------------------------
__global__ void __launch_bounds__(THREADS_PER_BLK, 3)
wigner_fused(const float* __restrict__ X1, const float* __restrict__ X2,
             const float* __restrict__ mult,
             const int* __restrict__ m1,  const int* __restrict__ m1p,
             const int* __restrict__ m2,  const int* __restrict__ m2p,
             const int* __restrict__ mub,
             float* __restrict__ out, int N, int n)
{
    __shared__ float sm[SMEM_WORDS];
    __shared__ __align__(16) uint4 s_gslot[49];
    __shared__ __align__(16) float s_D[KOUT * 8];
    __shared__ int s_focc[8];
    __shared__ int s_cnt[KOUT];
    __shared__ int s_sT[8];

    int tid  = threadIdx.x;
    int lane = tid & 31;
    int mu   = tid >> 5;
    int base = blockIdx.x * SAMPLES_PER_BLK;
    int nvalid = N - base; if (nvalid > SAMPLES_PER_BLK) nvalid = SAMPLES_PER_BLK;
    int total = nvalid * KOUT;
    bool full = (nvalid == SAMPLES_PER_BLK);

    const float* g1 = X1 + (size_t)base * KOUT;
    const float* g2 = X2 + (size_t)base * KOUT;

    // ---- init shared table state ----
    if (tid < 8)    s_focc[tid] = 0x7fffffff;
    if (tid < KOUT) { s_cnt[tid] = 0; s_gslot[tid] = make_uint4(0u,0u,0u,0u); }
    for (int i = tid; i < KOUT * 8; i += THREADS_PER_BLK) s_D[i] = 0.0f;

    // ---- issue X staging LDGs early (MLP=14); latency hides the table build
    float r1v[7], r2v[7];
    if (full) {
        #pragma unroll
        for (int k = 0; k < 7; k++) {
            int i = tid + k * THREADS_PER_BLK;
            r1v[k] = g1[i];
            r2v[k] = g2[i];
        }
    }
    __syncthreads();

    // ---- focc recovery: ONE round over the first <=224 aligned entries
    if (tid < n) {
        int v = mub[tid];
        if (v < 7) atomicMin(&s_focc[v], tid);
    }

    // ---- STS the X data (loads arrive under the atomic round)
    if (full) {
        #pragma unroll
        for (int k = 0; k < 7; k++) {
            int i = tid + k * THREADS_PER_BLK;
            int s = i / KOUT;
            int c = i - s * KOUT;
            sm[s * XSTR + c]      = r1v[k];
            sm[s * XSTR + 49 + c] = r2v[k];
        }
    }
    __syncthreads();

    if (tid == 0) {
        int Ttot = (int)(sqrtf((float)n) + 0.5f);   // n = Ttot^2 exactly
        s_focc[0] = 0;
        s_sT[7] = Ttot;
        for (int v = 0; v < 6; v++) s_sT[v] = s_focc[v + 1] - s_focc[v];
        s_sT[6] = Ttot - s_focc[6];
        for (int v = 0; v < 7; v++) if (s_sT[v] > MAXT) s_sT[v] = MAXT;
    }
    __syncthreads();

    // ---- build tables (one thread per (mu, t) slot; index arrays L2-hot)
    {
        float A = mult[0];
        int Ttot = s_sT[7];
        int t = lane;
        if (t < s_sT[mu]) {
            int j = Ttot * (s_focc[mu] + t);               // (mu, t, 0, 0)
            int r2 = m2[j];
            int pos = atomicAdd(&s_cnt[mu * 7 + r2], 1);
            if (pos < 2) {
                unsigned* slot = (unsigned*)&s_gslot[mu * 7 + r2];
                slot[pos * 2]     = (unsigned)(m1[j] * 28);    // byte off in 4B blob
                slot[pos * 2 + 1] = __float_as_uint(mult[j]);
            }
            int j2 = s_focc[mu] + t;                        // (0, 0, mup=mu, t')
            s_D[(m1p[j2] * 7 + m2p[j2]) * 8 + mu] = mult[j2] / A;  // unique -> plain store
        }
    }
    __syncthreads();
    // canonical slot order (deterministic regardless of atomic race)
    if (tid < 49) {
        uint4 e = s_gslot[tid];
        if (e.w != 0u && e.x > e.z) s_gslot[tid] = make_uint4(e.z, e.w, e.x, e.y);
    }

    // ---- slow-path staging for the tail block
    if (!full) {
        for (int i = tid; i < OBASE; i += THREADS_PER_BLK) sm[i] = 0.0f;
        __syncthreads();
        for (int i = tid; i < total; i += THREADS_PER_BLK) {
            int s = i / KOUT;
            int c = i - s * KOUT;
            sm[s * XSTR + c]      = g1[i];
            sm[s * XSTR + 49 + c] = g2[i];
        }
    }
    __syncthreads();

    // ============== compute core: single-pass W[49], scalar ==============
    {
        const char* xc = (const char*)(sm + lane * XSTR);
        const uint4* gs = s_gslot + mu * 7;

        float W[49];
        #pragma unroll
        for (int i = 0; i < 49; i++) W[i] = 0.0f;

        #pragma unroll 1
        for (int g = 0; g < 7; g++) {
            uint4 e = gs[g];                               // uniform LDS.128
            float c0 = __uint_as_float(e.y);
            float c1 = __uint_as_float(e.w);
            const float* ra = (const float*)(xc + e.x);
            const float* rb = (const float*)(xc + e.z);
            float u[7];
            #pragma unroll
            for (int a = 0; a < 7; a++)
                u[a] = fmaf(c1, rb[a], c0 * ra[a]);
            const float* r2 = (const float*)(xc + X2B + g * 28);
            #pragma unroll
            for (int b = 0; b < 7; b++) {
                float x = r2[b];
                #pragma unroll
                for (int a = 0; a < 7; a++)
                    W[a * 7 + b] = fmaf(u[a], x, W[a * 7 + b]);
            }
        }

        // dense D consume: W stays in registers (compile-time indices)
        float acc[7];
        #pragma unroll
        for (int q = 0; q < 7; q++) acc[q] = 0.0f;
        #pragma unroll
        for (int i = 0; i < 49; i++) {
            float4 d0 = *(const float4*)(s_D + i * 8);     // uniform broadcast
            float4 d1 = *(const float4*)(s_D + i * 8 + 4);
            float w = W[i];
            acc[0] = fmaf(d0.x, w, acc[0]);
            acc[1] = fmaf(d0.y, w, acc[1]);
            acc[2] = fmaf(d0.z, w, acc[2]);
            acc[3] = fmaf(d0.w, w, acc[3]);
            acc[4] = fmaf(d1.x, w, acc[4]);
            acc[5] = fmaf(d1.y, w, acc[5]);
            acc[6] = fmaf(d1.z, w, acc[6]);
        }

        // stage output transposed (stride 33 odd -> conflict-free)
        #pragma unroll
        for (int mup = 0; mup < 7; mup++)
            sm[OBASE + (mu * 7 + mup) * OUTSTR + lane] = acc[mup];
    }
    __syncthreads();

    // coalesced flush
    float* go = out + (size_t)base * KOUT;
    for (int i = tid; i < total; i += THREADS_PER_BLK) {
        int s = i / KOUT;
        int c = i - s * KOUT;
        go[i] = sm[OBASE + c * OUTSTR + s];
    }
}

// ---------------------------------------------------------------------------
extern "C" void kernel_launch(void* const* d_in, const int* in_sizes, int n_in,
                              void* d_out, int out_size)
{
    const float* X1   = (const float*)d_in[0];
    const float* X2   = (const float*)d_in[1];
    const float* mult = (const float*)d_in[2];
    const int*   m1   = (const int*)d_in[3];
    const int*   m1p  = (const int*)d_in[4];
    const int*   m2   = (const int*)d_in[5];
    const int*   m2p  = (const int*)d_in[6];
    const int*   mub  = (const int*)d_in[7];

    int n_aligned = in_sizes[2];
    int N = in_sizes[0] / KOUT;

    int grid = (N + SAMPLES_PER_BLK - 1) / SAMPLES_PER_BLK;
    wigner_fused<<<grid, THREADS_PER_BLK>>>(X1, X2, mult, m1, m1p, m2, m2p, mub,
                                            (float*)d_out, N, n_aligned);
}